// round 13
// baseline (speedup 1.0000x reference)
#include <cuda_runtime.h>
#include <cuda_fp16.h>
#include <cstdint>

// ThreeBodyLayer — round 13: round-12 pipeline + half-MUFU softplus.
// softplus(x) = max(x,0) + log1p(exp(-|x|)): exp via ex2.approx (1 MUFU),
// log1p via degree-6 Chebyshev polynomial on t in (0,1] (7 FMA, abs err
// ~2e-6, far below fp16-h quantization). MUFU pressure halves; the work
// moves to the 23%-utilized FMA pipe. Everything else identical to R12:
// 192-thr CTAs x2/SM, 12-row groups, fp16 MMA, software-pipelined phases
// with double-buffered fp16 cab, 1 barrier per group.

#define FULLMASK 0xFFFFFFFFu

__device__ __forceinline__ float softplus_f(float x) {
    float t;   // t = exp(-|x|) in (0,1]
    asm("ex2.approx.ftz.f32 %0, %1;"
        : "=f"(t) : "f"(fabsf(x) * -1.4426950408889634f));
    // log1p(t) on [0,1]: Chebyshev-derived degree-6 poly in s = 2t-1
    float s = fmaf(2.0f, t, -1.0f);
    float p = fmaf(-0.000272111f, s, 0.000951512f);
    p = fmaf(p, s, -0.00305802f);
    p = fmaf(p, s,  0.01227897f);
    p = fmaf(p, s, -0.05556138f);
    p = fmaf(p, s,  0.33334188f);
    p = fmaf(p, s,  0.40546548f);
    return fmaxf(x, 0.0f) + p;
}
__device__ __forceinline__ uint32_t smem_u32(const void* p) {
    uint32_t a;
    asm("{ .reg .u64 t; cvta.to.shared.u64 t, %1; cvt.u32.u64 %0, t; }"
        : "=r"(a) : "l"(p));
    return a;
}
__device__ __forceinline__ uint32_t pkhf(float a, float b) {   // hi=a, lo=b
    uint32_t r; asm("cvt.rn.f16x2.f32 %0, %1, %2;" : "=r"(r) : "f"(a), "f"(b));
    return r;
}
__device__ __forceinline__ void ldsm4(uint32_t* r, uint32_t addr) {
    asm volatile("ldmatrix.sync.aligned.m8n8.x4.shared.b16 {%0,%1,%2,%3}, [%4];"
                 : "=r"(r[0]), "=r"(r[1]), "=r"(r[2]), "=r"(r[3]) : "r"(addr));
}
__device__ __forceinline__ void mma_f16(float* c, const uint32_t* a,
                                        uint32_t b0, uint32_t b1) {
    asm volatile(
        "mma.sync.aligned.m16n8k16.row.col.f32.f16.f16.f32 "
        "{%0,%1,%2,%3}, {%4,%5,%6,%7}, {%8,%9}, {%0,%1,%2,%3};"
        : "+f"(c[0]), "+f"(c[1]), "+f"(c[2]), "+f"(c[3])
        : "r"(a[0]), "r"(a[1]), "r"(a[2]), "r"(a[3]), "r"(b0), "r"(b1));
}

// ---- SMEM layout (bytes) per 192-thread CTA ----
static constexpr int S_W1H   = 0;        // W1^T fp16 [192 n'][64 k]   24576
static constexpr int S_CAB   = 24576;    // fp16 cab x2 buffers        39936
static constexpr int CAB_BUF = 19968;    //   12 rows * 13 vecs * 128B
static constexpr int S_H     = 64512;    // h: 6 warps x 32x128B       24576
static constexpr int SMEM_BYTES = 89088;

static constexpr int RPG = 12;           // rows per group

__global__ void __launch_bounds__(192, 2) three_body_kernel(
    const float* __restrict__ core,   // [B, 64]
    const float* __restrict__ ligs,   // [B, 6, 64]
    const float* __restrict__ W1,     // [192, 64]
    const float* __restrict__ b1,     // [64]
    const float* __restrict__ W2,     // [64, 32]
    const float* __restrict__ b2,     // [32]
    const float* __restrict__ W3,     // [32]
    const float* __restrict__ b3,     // [1]
    float* __restrict__ out,          // [B]
    int B)
{
    extern __shared__ unsigned char sm[];
    const uint32_t smem_base = smem_u32(sm);
    const int tid  = threadIdx.x;
    const int lane = tid & 31;
    const int wid  = tid >> 5;        // 0..5

    // ---- stage W1^T (fp16, swizzled 128B rows) ----
    for (int idx = tid; idx < 12288; idx += 192) {
        int n = idx >> 6, k = idx & 63;
        float w;
        if      (n < 64)  w = W1[(64  + k) * 64 + n];
        else if (n < 128) w = W1[(128 + k) * 64 + (n - 64)];
        else              w = W1[k * 64 + (n - 128)];
        int byte = n * 128 + ((2 * k) ^ ((n & 7) << 4));
        *reinterpret_cast<__half*>(sm + S_W1H + byte) = __float2half_rn(w);
    }

    // ---- W2 fragments in registers (fp16) ----
    uint32_t B1f[4][4][2];
    {
        const int krow = (lane & 3) * 2;
        const int ncol = lane >> 2;
        #pragma unroll
        for (int kt = 0; kt < 4; kt++)
            #pragma unroll
            for (int nt = 0; nt < 4; nt++) {
                int k0 = kt * 16 + krow, n = nt * 8 + ncol;
                B1f[kt][nt][0] = pkhf(W2[(k0 + 1) * 32 + n], W2[(k0 + 0) * 32 + n]);
                B1f[kt][nt][1] = pkhf(W2[(k0 + 9) * 32 + n], W2[(k0 + 8) * 32 + n]);
            }
    }
    float b2v[8], w3v[8];
    #pragma unroll
    for (int nt = 0; nt < 4; nt++)
        #pragma unroll
        for (int e = 0; e < 2; e++) {
            int n = nt * 8 + (lane & 3) * 2 + e;
            b2v[nt * 2 + e] = b2[n];
            w3v[nt * 2 + e] = W3[n];
        }
    int pi, pj;
    if (lane < 30) { pi = lane / 5; int jj = lane % 5; pj = jj + (jj >= pi ? 1 : 0); }
    else           { pi = 0; pj = 1; }

    const float b3v = b3[0];
    const int r0  = lane >> 2;            // fragment row in m16 (0..7)
    const int c0  = (lane & 3) * 2;       // fragment col pair base
    const uint32_t lsw   = (uint32_t)(lane & 7) << 4;
    const uint32_t csel  = (uint32_t)(lane >> 4) * 16;
    const uint32_t w1row = (uint32_t)(lane & 15) * 128;
    const uint32_t w1baseH = smem_base + S_W1H;
    const uint32_t hbl  = smem_base + S_H + wid * 4096;
    char* hrow = (char*)sm + S_H + wid * 4096 + lane * 128;
    const uint32_t hsw = (uint32_t)(lane & 7) << 4;

    const int n_groups = (B + RPG - 1) / RPG;   // 2731

    // ---- phase 1: layer-1 GEMMs for group at rbase, into cab buffer cb ----
    auto phase1 = [&](int rbase, char* cb) {
        {   // ligand k = wid, M=16 tile (rows 0..11 real, 12..15 clamped)
            const int k  = wid;
            const int ra = rbase + r0;
            const int rb8 = rbase + r0 + 8;
            const int rb = (rb8 < B) ? rb8 : (B - 1);
            const float* xa = ligs + (size_t)ra * 384 + k * 64;
            const float* xb = ligs + (size_t)rb * 384 + k * 64;
            uint32_t af[4][4];
            #pragma unroll
            for (int kt = 0; kt < 4; kt++) {
                int c = kt * 16 + c0;
                float2 x00 = *reinterpret_cast<const float2*>(xa + c);
                float2 x10 = *reinterpret_cast<const float2*>(xb + c);
                float2 x01 = *reinterpret_cast<const float2*>(xa + c + 8);
                float2 x11 = *reinterpret_cast<const float2*>(xb + c + 8);
                af[kt][0] = pkhf(x00.y, x00.x);  af[kt][1] = pkhf(x10.y, x10.x);
                af[kt][2] = pkhf(x01.y, x01.x);  af[kt][3] = pkhf(x11.y, x11.x);
            }
            #pragma unroll
            for (int np = 0; np < 8; np++) {
                float a0[4] = {0.f, 0.f, 0.f, 0.f}, a1[4] = {0.f, 0.f, 0.f, 0.f};
                #pragma unroll
                for (int kt = 0; kt < 4; kt++) {
                    uint32_t bh[4];
                    uint32_t adr = w1baseH + (uint32_t)np * 2048 + w1row
                                 + (((uint32_t)kt * 32 + csel) ^ lsw);
                    ldsm4(bh, adr);
                    mma_f16(a0, af[kt], bh[0], bh[2]);
                    mma_f16(a1, af[kt], bh[1], bh[3]);
                }
                #pragma unroll
                for (int ntl = 0; ntl < 2; ntl++) {
                    const float* a = ntl ? a1 : a0;
                    int n = np * 16 + ntl * 8 + c0;
                    int d = n & 63;
                    int vec = (n < 64) ? k : 6 + k;
                    uint32_t v0 = pkhf(a[1], a[0]);        // lo = d, hi = d+1
                    uint32_t v1 = pkhf(a[3], a[2]);
                    uint32_t off0 = (uint32_t)(2 * d)
                                  ^ ((uint32_t)((vec ^ r0) & 7) << 4);
                    *reinterpret_cast<uint32_t*>(
                        cb + r0 * 1664 + vec * 128 + off0) = v0;
                    if (r0 < 4) {
                        uint32_t off1 = (uint32_t)(2 * d)
                                      ^ ((uint32_t)((vec ^ (r0 + 8)) & 7) << 4);
                        *reinterpret_cast<uint32_t*>(
                            cb + (r0 + 8) * 1664 + vec * 128 + off1) = v1;
                    }
                }
            }
        }
        if (wid < 4) {   // core projection (+b1): n-tile np = wid (n == d)
            const int np = wid;
            const int ra = rbase + r0;
            const int rb8 = rbase + r0 + 8;
            const int rb = (rb8 < B) ? rb8 : (B - 1);
            const float* xa = core + (size_t)ra * 64;
            const float* xb = core + (size_t)rb * 64;
            uint32_t af[4][4];
            #pragma unroll
            for (int kt = 0; kt < 4; kt++) {
                int c = kt * 16 + c0;
                float2 x00 = *reinterpret_cast<const float2*>(xa + c);
                float2 x10 = *reinterpret_cast<const float2*>(xb + c);
                float2 x01 = *reinterpret_cast<const float2*>(xa + c + 8);
                float2 x11 = *reinterpret_cast<const float2*>(xb + c + 8);
                af[kt][0] = pkhf(x00.y, x00.x);  af[kt][1] = pkhf(x10.y, x10.x);
                af[kt][2] = pkhf(x01.y, x01.x);  af[kt][3] = pkhf(x11.y, x11.x);
            }
            float a0[4] = {0.f, 0.f, 0.f, 0.f}, a1[4] = {0.f, 0.f, 0.f, 0.f};
            #pragma unroll
            for (int kt = 0; kt < 4; kt++) {
                uint32_t bh[4];
                uint32_t adr = w1baseH + (uint32_t)(128 + np * 16) * 128 + w1row
                             + (((uint32_t)kt * 32 + csel) ^ lsw);
                ldsm4(bh, adr);
                mma_f16(a0, af[kt], bh[0], bh[2]);
                mma_f16(a1, af[kt], bh[1], bh[3]);
            }
            #pragma unroll
            for (int ntl = 0; ntl < 2; ntl++) {
                const float* a = ntl ? a1 : a0;
                int d = np * 16 + ntl * 8 + c0;
                float bb0 = __ldg(b1 + d), bb1 = __ldg(b1 + d + 1);
                uint32_t v0 = pkhf(a[1] + bb1, a[0] + bb0);
                uint32_t v1 = pkhf(a[3] + bb1, a[2] + bb0);
                uint32_t off0 = (uint32_t)(2 * d)
                              ^ ((uint32_t)((12 ^ r0) & 7) << 4);
                *reinterpret_cast<uint32_t*>(
                    cb + r0 * 1664 + 12 * 128 + off0) = v0;
                if (r0 < 4) {
                    uint32_t off1 = (uint32_t)(2 * d)
                                  ^ ((uint32_t)((12 ^ (r0 + 8)) & 7) << 4);
                    *reinterpret_cast<uint32_t*>(
                        cb + (r0 + 8) * 1664 + 12 * 128 + off1) = v1;
                }
            }
        }
    };

    // ---- phase 2: h-build + layer-2 GEMM + epilogue for group at rbase ----
    auto phase2 = [&](int rbase, const char* cb) {
        #pragma unroll
        for (int rr = 0; rr < 2; rr++) {
            const int row = wid * 2 + rr;
            const char* rowb = cb + row * 1664;
            const char* bA = rowb + pi * 128;
            const char* bB = rowb + (6 + pj) * 128;
            const char* bC = rowb + 12 * 128;
            const uint32_t swA = (uint32_t)((pi ^ row) & 7) << 4;
            const uint32_t swB = (uint32_t)(((6 + pj) ^ row) & 7) << 4;
            const uint32_t swC = (uint32_t)((12 ^ row) & 7) << 4;

            #pragma unroll
            for (int q2 = 0; q2 < 8; q2++) {
                const uint32_t qb = (uint32_t)q2 * 16;
                uint4 ua = *reinterpret_cast<const uint4*>(bA + (qb ^ swA));
                uint4 ub = *reinterpret_cast<const uint4*>(bB + (qb ^ swB));
                uint4 uc = *reinterpret_cast<const uint4*>(bC + (qb ^ swC));
                const __half2* ha = reinterpret_cast<const __half2*>(&ua);
                const __half2* hb2 = reinterpret_cast<const __half2*>(&ub);
                const __half2* hc = reinterpret_cast<const __half2*>(&uc);
                uint32_t hw[4];
                #pragma unroll
                for (int w = 0; w < 4; w++) {
                    float2 fa = __half22float2(ha[w]);
                    float2 fb = __half22float2(hb2[w]);
                    float2 fc = __half22float2(hc[w]);
                    float s0 = fa.x + fb.x + fc.x;
                    float s1 = fa.y + fb.y + fc.y;
                    hw[w] = pkhf(softplus_f(s1), softplus_f(s0));
                }
                *reinterpret_cast<uint4*>(hrow + (qb ^ hsw)) =
                    make_uint4(hw[0], hw[1], hw[2], hw[3]);
            }
            __syncwarp();

            float acc[2][4][4];
            #pragma unroll
            for (int mt = 0; mt < 2; mt++)
                #pragma unroll
                for (int nt = 0; nt < 4; nt++)
                    #pragma unroll
                    for (int e = 0; e < 4; e++) acc[mt][nt][e] = 0.0f;

            #pragma unroll
            for (int mt = 0; mt < 2; mt++)
                #pragma unroll
                for (int kt = 0; kt < 4; kt++) {
                    uint32_t afr[4];
                    uint32_t adr = hbl + (uint32_t)mt * 2048 + w1row
                                 + (((uint32_t)kt * 32 + csel) ^ lsw);
                    ldsm4(afr, adr);
                    #pragma unroll
                    for (int nt = 0; nt < 4; nt++)
                        mma_f16(acc[mt][nt], afr, B1f[kt][nt][0], B1f[kt][nt][1]);
                }

            float total = 0.0f;
            #pragma unroll
            for (int mt = 0; mt < 2; mt++)
                #pragma unroll
                for (int hf = 0; hf < 2; hf++) {
                    int prow = mt * 16 + (lane >> 2) + hf * 8;
                    float part = 0.0f;
                    #pragma unroll
                    for (int nt = 0; nt < 4; nt++)
                        #pragma unroll
                        for (int e = 0; e < 2; e++)
                            part += softplus_f(acc[mt][nt][hf * 2 + e] + b2v[nt * 2 + e])
                                    * w3v[nt * 2 + e];
                    if (prow < 30) total += part;
                }
            #pragma unroll
            for (int off = 16; off; off >>= 1)
                total += __shfl_xor_sync(FULLMASK, total, off);
            const int gr = rbase + row;
            if (lane == 0 && gr < B)
                out[gr] = 0.5f * total + 15.0f * b3v;
            __syncwarp();   // h buffer free before next row overwrites it
        }
    };

    __syncthreads();   // W1 staged

    // ---- pipelined main loop: 1 barrier per group ----
    char* cab = (char*)sm + S_CAB;
    int g = blockIdx.x;
    if (g < n_groups) phase1(g * RPG, cab);         // prologue -> buffer 0
    int it = 0;
    for (; g < n_groups; g += gridDim.x, it++) {
        __syncthreads();   // prev phase1 (buf it&1) + prev phase2 (buf (it+1)&1) done
        int gn = g + gridDim.x;
        if (gn < n_groups) phase1(gn * RPG, cab + ((it + 1) & 1) * CAB_BUF);
        phase2(g * RPG, cab + (it & 1) * CAB_BUF);
    }
}

extern "C" void kernel_launch(void* const* d_in, const int* in_sizes, int n_in,
                              void* d_out, int out_size) {
    const float* core = (const float*)d_in[0];
    const float* ligs = (const float*)d_in[1];
    const float* W1   = (const float*)d_in[2];
    const float* b1   = (const float*)d_in[3];
    const float* W2   = (const float*)d_in[4];
    const float* b2   = (const float*)d_in[5];
    const float* W3   = (const float*)d_in[6];
    const float* b3   = (const float*)d_in[7];
    float* out = (float*)d_out;

    const int B = in_sizes[0] / 64;   // 32768

    cudaFuncSetAttribute(three_body_kernel,
                         cudaFuncAttributeMaxDynamicSharedMemorySize, SMEM_BYTES);

    // 296 CTAs = 2 per SM (89KB SMEM each); grid-stride over 2731 groups.
    three_body_kernel<<<296, 192, SMEM_BYTES>>>(
        core, ligs, W1, b1, W2, b2, W3, b3, out, B);
}

// round 14
// speedup vs baseline: 1.1996x; 1.1996x over previous
#include <cuda_runtime.h>
#include <cuda_fp16.h>
#include <cstdint>

// ThreeBodyLayer — round 14: R12 pipeline + packed-half2 softplus h-build +
// double-buffered h. Epilogue softplus reverted to the proven R12 fp32 form
// (R13's poly traded 1 MUFU for 7 FMA issue-slots and regressed: the kernel
// is issue-bound, so only net instruction-count cuts pay).
//
// h-build: s = CA_i + B_j + cp entirely in half2 (2 HADD2), softplus_h2 =
// h2exp2 (1 MUFU / 2 values) + degree-4 log1p poly (4 HFMA2) + HMAX2/HADD2.
// ~10 issue-slots per 2 h values vs ~19 before. h double-buffered per warp
// (8KB) so row 0's MMA/epilogue overlaps row 1's h-build; trailing syncwarp
// dropped (group-level __syncthreads covers cross-group reuse).

#define FULLMASK 0xFFFFFFFFu

__device__ __forceinline__ float softplus_f(float x) {
    return fmaxf(x, 0.0f) + __logf(1.0f + __expf(-fabsf(x)));
}
// packed softplus: per half2, 1 MUFU + ~9 half2 ALU ops
__device__ __forceinline__ __half2 softplus_h2(__half2 s) {
    const __half2 nl2e = __float2half2_rn(-1.4426950408889634f);
    __half2 t = h2exp2(__hmul2(__habs2(s), nl2e));          // exp(-|s|)
    // log1p(t), t in (0,1]: Chebyshev-derived degree-4 poly in u = 2t-1
    // p(1)=ln2, p(-1)=9.5e-5; truncation err ~6e-5 (<< fp16 rounding)
    __half2 u = __hfma2(__float2half2_rn(2.0f), t, __float2half2_rn(-1.0f));
    __half2 p = __hfma2(__float2half2_rn(-0.003464f), u,
                        __float2half2_rn( 0.013468f));
    p = __hfma2(p, u, __float2half2_rn(-0.055410f));
    p = __hfma2(p, u, __float2half2_rn( 0.333045f));
    p = __hfma2(p, u, __float2half2_rn( 0.405482f));
    return __hadd2(__hmax2(s, __float2half2_rn(0.0f)), p);
}
__device__ __forceinline__ uint32_t smem_u32(const void* p) {
    uint32_t a;
    asm("{ .reg .u64 t; cvta.to.shared.u64 t, %1; cvt.u32.u64 %0, t; }"
        : "=r"(a) : "l"(p));
    return a;
}
__device__ __forceinline__ uint32_t pkhf(float a, float b) {   // hi=a, lo=b
    uint32_t r; asm("cvt.rn.f16x2.f32 %0, %1, %2;" : "=r"(r) : "f"(a), "f"(b));
    return r;
}
__device__ __forceinline__ void ldsm4(uint32_t* r, uint32_t addr) {
    asm volatile("ldmatrix.sync.aligned.m8n8.x4.shared.b16 {%0,%1,%2,%3}, [%4];"
                 : "=r"(r[0]), "=r"(r[1]), "=r"(r[2]), "=r"(r[3]) : "r"(addr));
}
__device__ __forceinline__ void mma_f16(float* c, const uint32_t* a,
                                        uint32_t b0, uint32_t b1) {
    asm volatile(
        "mma.sync.aligned.m16n8k16.row.col.f32.f16.f16.f32 "
        "{%0,%1,%2,%3}, {%4,%5,%6,%7}, {%8,%9}, {%0,%1,%2,%3};"
        : "+f"(c[0]), "+f"(c[1]), "+f"(c[2]), "+f"(c[3])
        : "r"(a[0]), "r"(a[1]), "r"(a[2]), "r"(a[3]), "r"(b0), "r"(b1));
}

// ---- SMEM layout (bytes) per 192-thread CTA ----
static constexpr int S_W1H   = 0;        // W1^T fp16 [192 n'][64 k]   24576
static constexpr int S_CAB   = 24576;    // fp16 cab x2 buffers        39936
static constexpr int CAB_BUF = 19968;    //   12 rows * 13 vecs * 128B
static constexpr int S_H     = 64512;    // h: 6 warps x 2 x 32x128B   49152
static constexpr int SMEM_BYTES = 113664;

static constexpr int RPG = 12;           // rows per group

__global__ void __launch_bounds__(192, 2) three_body_kernel(
    const float* __restrict__ core,   // [B, 64]
    const float* __restrict__ ligs,   // [B, 6, 64]
    const float* __restrict__ W1,     // [192, 64]
    const float* __restrict__ b1,     // [64]
    const float* __restrict__ W2,     // [64, 32]
    const float* __restrict__ b2,     // [32]
    const float* __restrict__ W3,     // [32]
    const float* __restrict__ b3,     // [1]
    float* __restrict__ out,          // [B]
    int B)
{
    extern __shared__ unsigned char sm[];
    const uint32_t smem_base = smem_u32(sm);
    const int tid  = threadIdx.x;
    const int lane = tid & 31;
    const int wid  = tid >> 5;        // 0..5

    // ---- stage W1^T (fp16, swizzled 128B rows) ----
    for (int idx = tid; idx < 12288; idx += 192) {
        int n = idx >> 6, k = idx & 63;
        float w;
        if      (n < 64)  w = W1[(64  + k) * 64 + n];
        else if (n < 128) w = W1[(128 + k) * 64 + (n - 64)];
        else              w = W1[k * 64 + (n - 128)];
        int byte = n * 128 + ((2 * k) ^ ((n & 7) << 4));
        *reinterpret_cast<__half*>(sm + S_W1H + byte) = __float2half_rn(w);
    }

    // ---- W2 fragments in registers (fp16) ----
    uint32_t B1f[4][4][2];
    {
        const int krow = (lane & 3) * 2;
        const int ncol = lane >> 2;
        #pragma unroll
        for (int kt = 0; kt < 4; kt++)
            #pragma unroll
            for (int nt = 0; nt < 4; nt++) {
                int k0 = kt * 16 + krow, n = nt * 8 + ncol;
                B1f[kt][nt][0] = pkhf(W2[(k0 + 1) * 32 + n], W2[(k0 + 0) * 32 + n]);
                B1f[kt][nt][1] = pkhf(W2[(k0 + 9) * 32 + n], W2[(k0 + 8) * 32 + n]);
            }
    }
    float b2v[8], w3v[8];
    #pragma unroll
    for (int nt = 0; nt < 4; nt++)
        #pragma unroll
        for (int e = 0; e < 2; e++) {
            int n = nt * 8 + (lane & 3) * 2 + e;
            b2v[nt * 2 + e] = b2[n];
            w3v[nt * 2 + e] = W3[n];
        }
    int pi, pj;
    if (lane < 30) { pi = lane / 5; int jj = lane % 5; pj = jj + (jj >= pi ? 1 : 0); }
    else           { pi = 0; pj = 1; }

    const float b3v = b3[0];
    const int r0  = lane >> 2;            // fragment row in m16 (0..7)
    const int c0  = (lane & 3) * 2;       // fragment col pair base
    const uint32_t lsw   = (uint32_t)(lane & 7) << 4;
    const uint32_t csel  = (uint32_t)(lane >> 4) * 16;
    const uint32_t w1row = (uint32_t)(lane & 15) * 128;
    const uint32_t w1baseH = smem_base + S_W1H;
    const uint32_t hbl  = smem_base + S_H + wid * 8192;
    char* hrow = (char*)sm + S_H + wid * 8192 + lane * 128;
    const uint32_t hsw = (uint32_t)(lane & 7) << 4;

    const int n_groups = (B + RPG - 1) / RPG;   // 2731

    // ---- phase 1: layer-1 GEMMs for group at rbase, into cab buffer cb ----
    auto phase1 = [&](int rbase, char* cb) {
        {   // ligand k = wid, M=16 tile (rows 0..11 real, 12..15 clamped)
            const int k  = wid;
            const int ra = rbase + r0;
            const int rb8 = rbase + r0 + 8;
            const int rb = (rb8 < B) ? rb8 : (B - 1);
            const float* xa = ligs + (size_t)ra * 384 + k * 64;
            const float* xb = ligs + (size_t)rb * 384 + k * 64;
            uint32_t af[4][4];
            #pragma unroll
            for (int kt = 0; kt < 4; kt++) {
                int c = kt * 16 + c0;
                float2 x00 = *reinterpret_cast<const float2*>(xa + c);
                float2 x10 = *reinterpret_cast<const float2*>(xb + c);
                float2 x01 = *reinterpret_cast<const float2*>(xa + c + 8);
                float2 x11 = *reinterpret_cast<const float2*>(xb + c + 8);
                af[kt][0] = pkhf(x00.y, x00.x);  af[kt][1] = pkhf(x10.y, x10.x);
                af[kt][2] = pkhf(x01.y, x01.x);  af[kt][3] = pkhf(x11.y, x11.x);
            }
            #pragma unroll
            for (int np = 0; np < 8; np++) {
                float a0[4] = {0.f, 0.f, 0.f, 0.f}, a1[4] = {0.f, 0.f, 0.f, 0.f};
                #pragma unroll
                for (int kt = 0; kt < 4; kt++) {
                    uint32_t bh[4];
                    uint32_t adr = w1baseH + (uint32_t)np * 2048 + w1row
                                 + (((uint32_t)kt * 32 + csel) ^ lsw);
                    ldsm4(bh, adr);
                    mma_f16(a0, af[kt], bh[0], bh[2]);
                    mma_f16(a1, af[kt], bh[1], bh[3]);
                }
                #pragma unroll
                for (int ntl = 0; ntl < 2; ntl++) {
                    const float* a = ntl ? a1 : a0;
                    int n = np * 16 + ntl * 8 + c0;
                    int d = n & 63;
                    int vec = (n < 64) ? k : 6 + k;
                    uint32_t v0 = pkhf(a[1], a[0]);        // lo = d, hi = d+1
                    uint32_t v1 = pkhf(a[3], a[2]);
                    uint32_t off0 = (uint32_t)(2 * d)
                                  ^ ((uint32_t)((vec ^ r0) & 7) << 4);
                    *reinterpret_cast<uint32_t*>(
                        cb + r0 * 1664 + vec * 128 + off0) = v0;
                    if (r0 < 4) {
                        uint32_t off1 = (uint32_t)(2 * d)
                                      ^ ((uint32_t)((vec ^ (r0 + 8)) & 7) << 4);
                        *reinterpret_cast<uint32_t*>(
                            cb + (r0 + 8) * 1664 + vec * 128 + off1) = v1;
                    }
                }
            }
        }
        if (wid < 4) {   // core projection (+b1): n-tile np = wid (n == d)
            const int np = wid;
            const int ra = rbase + r0;
            const int rb8 = rbase + r0 + 8;
            const int rb = (rb8 < B) ? rb8 : (B - 1);
            const float* xa = core + (size_t)ra * 64;
            const float* xb = core + (size_t)rb * 64;
            uint32_t af[4][4];
            #pragma unroll
            for (int kt = 0; kt < 4; kt++) {
                int c = kt * 16 + c0;
                float2 x00 = *reinterpret_cast<const float2*>(xa + c);
                float2 x10 = *reinterpret_cast<const float2*>(xb + c);
                float2 x01 = *reinterpret_cast<const float2*>(xa + c + 8);
                float2 x11 = *reinterpret_cast<const float2*>(xb + c + 8);
                af[kt][0] = pkhf(x00.y, x00.x);  af[kt][1] = pkhf(x10.y, x10.x);
                af[kt][2] = pkhf(x01.y, x01.x);  af[kt][3] = pkhf(x11.y, x11.x);
            }
            float a0[4] = {0.f, 0.f, 0.f, 0.f}, a1[4] = {0.f, 0.f, 0.f, 0.f};
            #pragma unroll
            for (int kt = 0; kt < 4; kt++) {
                uint32_t bh[4];
                uint32_t adr = w1baseH + (uint32_t)(128 + np * 16) * 128 + w1row
                             + (((uint32_t)kt * 32 + csel) ^ lsw);
                ldsm4(bh, adr);
                mma_f16(a0, af[kt], bh[0], bh[2]);
                mma_f16(a1, af[kt], bh[1], bh[3]);
            }
            #pragma unroll
            for (int ntl = 0; ntl < 2; ntl++) {
                const float* a = ntl ? a1 : a0;
                int d = np * 16 + ntl * 8 + c0;
                float bb0 = __ldg(b1 + d), bb1 = __ldg(b1 + d + 1);
                uint32_t v0 = pkhf(a[1] + bb1, a[0] + bb0);
                uint32_t v1 = pkhf(a[3] + bb1, a[2] + bb0);
                uint32_t off0 = (uint32_t)(2 * d)
                              ^ ((uint32_t)((12 ^ r0) & 7) << 4);
                *reinterpret_cast<uint32_t*>(
                    cb + r0 * 1664 + 12 * 128 + off0) = v0;
                if (r0 < 4) {
                    uint32_t off1 = (uint32_t)(2 * d)
                                  ^ ((uint32_t)((12 ^ (r0 + 8)) & 7) << 4);
                    *reinterpret_cast<uint32_t*>(
                        cb + (r0 + 8) * 1664 + 12 * 128 + off1) = v1;
                }
            }
        }
    };

    // ---- phase 2: h-build + layer-2 GEMM + epilogue for group at rbase ----
    auto phase2 = [&](int rbase, const char* cb) {
        #pragma unroll
        for (int rr = 0; rr < 2; rr++) {
            const int row = wid * 2 + rr;
            const char* rowb = cb + row * 1664;
            const char* bA = rowb + pi * 128;
            const char* bB = rowb + (6 + pj) * 128;
            const char* bC = rowb + 12 * 128;
            const uint32_t swA = (uint32_t)((pi ^ row) & 7) << 4;
            const uint32_t swB = (uint32_t)(((6 + pj) ^ row) & 7) << 4;
            const uint32_t swC = (uint32_t)((12 ^ row) & 7) << 4;
            char* hrow_r = hrow + rr * 4096;            // double-buffered h
            const uint32_t hbl_r = hbl + (uint32_t)rr * 4096;

            #pragma unroll
            for (int q2 = 0; q2 < 8; q2++) {
                const uint32_t qb = (uint32_t)q2 * 16;
                uint4 ua = *reinterpret_cast<const uint4*>(bA + (qb ^ swA));
                uint4 ub = *reinterpret_cast<const uint4*>(bB + (qb ^ swB));
                uint4 uc = *reinterpret_cast<const uint4*>(bC + (qb ^ swC));
                const __half2* ha = reinterpret_cast<const __half2*>(&ua);
                const __half2* hb2 = reinterpret_cast<const __half2*>(&ub);
                const __half2* hc = reinterpret_cast<const __half2*>(&uc);
                uint32_t hw[4];
                #pragma unroll
                for (int w = 0; w < 4; w++) {
                    __half2 s = __hadd2(__hadd2(ha[w], hb2[w]), hc[w]);
                    __half2 r = softplus_h2(s);
                    hw[w] = *reinterpret_cast<uint32_t*>(&r);
                }
                *reinterpret_cast<uint4*>(hrow_r + (qb ^ hsw)) =
                    make_uint4(hw[0], hw[1], hw[2], hw[3]);
            }
            __syncwarp();

            float acc[2][4][4];
            #pragma unroll
            for (int mt = 0; mt < 2; mt++)
                #pragma unroll
                for (int nt = 0; nt < 4; nt++)
                    #pragma unroll
                    for (int e = 0; e < 4; e++) acc[mt][nt][e] = 0.0f;

            #pragma unroll
            for (int mt = 0; mt < 2; mt++)
                #pragma unroll
                for (int kt = 0; kt < 4; kt++) {
                    uint32_t afr[4];
                    uint32_t adr = hbl_r + (uint32_t)mt * 2048 + w1row
                                 + (((uint32_t)kt * 32 + csel) ^ lsw);
                    ldsm4(afr, adr);
                    #pragma unroll
                    for (int nt = 0; nt < 4; nt++)
                        mma_f16(acc[mt][nt], afr, B1f[kt][nt][0], B1f[kt][nt][1]);
                }

            float total = 0.0f;
            #pragma unroll
            for (int mt = 0; mt < 2; mt++)
                #pragma unroll
                for (int hf = 0; hf < 2; hf++) {
                    int prow = mt * 16 + (lane >> 2) + hf * 8;
                    float part = 0.0f;
                    #pragma unroll
                    for (int nt = 0; nt < 4; nt++)
                        #pragma unroll
                        for (int e = 0; e < 2; e++)
                            part += softplus_f(acc[mt][nt][hf * 2 + e] + b2v[nt * 2 + e])
                                    * w3v[nt * 2 + e];
                    if (prow < 30) total += part;
                }
            #pragma unroll
            for (int off = 16; off; off >>= 1)
                total += __shfl_xor_sync(FULLMASK, total, off);
            const int gr = rbase + row;
            if (lane == 0 && gr < B)
                out[gr] = 0.5f * total + 15.0f * b3v;
        }
    };

    __syncthreads();   // W1 staged

    // ---- pipelined main loop: 1 barrier per group ----
    char* cab = (char*)sm + S_CAB;
    int g = blockIdx.x;
    if (g < n_groups) phase1(g * RPG, cab);         // prologue -> buffer 0
    int it = 0;
    for (; g < n_groups; g += gridDim.x, it++) {
        __syncthreads();   // prev phase1 (buf it&1) + prev phase2 (buf (it+1)&1) done
        int gn = g + gridDim.x;
        if (gn < n_groups) phase1(gn * RPG, cab + ((it + 1) & 1) * CAB_BUF);
        phase2(g * RPG, cab + (it & 1) * CAB_BUF);
    }
}

extern "C" void kernel_launch(void* const* d_in, const int* in_sizes, int n_in,
                              void* d_out, int out_size) {
    const float* core = (const float*)d_in[0];
    const float* ligs = (const float*)d_in[1];
    const float* W1   = (const float*)d_in[2];
    const float* b1   = (const float*)d_in[3];
    const float* W2   = (const float*)d_in[4];
    const float* b2   = (const float*)d_in[5];
    const float* W3   = (const float*)d_in[6];
    const float* b3   = (const float*)d_in[7];
    float* out = (float*)d_out;

    const int B = in_sizes[0] / 64;   // 32768

    cudaFuncSetAttribute(three_body_kernel,
                         cudaFuncAttributeMaxDynamicSharedMemorySize, SMEM_BYTES);

    // 296 CTAs = 2 per SM (113.7KB SMEM each); grid-stride over 2731 groups.
    three_body_kernel<<<296, 192, SMEM_BYTES>>>(
        core, ligs, W1, b1, W2, b2, W3, b3, out, B);
}

// round 15
// speedup vs baseline: 1.2623x; 1.0523x over previous
#include <cuda_runtime.h>
#include <cuda_fp16.h>
#include <cstdint>

// ThreeBodyLayer — round 15: 16 warps/SM (256-thr CTAs x2/SM, 16-row groups).
// Register diet to <=128 regs: W2 fragments via SMEM ldsm (not registers),
// epilogue b2/W3 via __ldg. RPG=16 divides B exactly -> all row clamping
// removed. Otherwise R14's proven pieces: fp16 MMA both layers, fp16 cab
// double-buffered, software-pipelined phases (1 barrier/group), packed
// half2 softplus in the h-build, fp32 softplus epilogue.

#define FULLMASK 0xFFFFFFFFu

__device__ __forceinline__ float softplus_f(float x) {
    return fmaxf(x, 0.0f) + __logf(1.0f + __expf(-fabsf(x)));
}
// packed softplus: per half2, 1 MUFU + ~9 half2 ALU ops
__device__ __forceinline__ __half2 softplus_h2(__half2 s) {
    const __half2 nl2e = __float2half2_rn(-1.4426950408889634f);
    __half2 t = h2exp2(__hmul2(__habs2(s), nl2e));          // exp(-|s|)
    __half2 u = __hfma2(__float2half2_rn(2.0f), t, __float2half2_rn(-1.0f));
    __half2 p = __hfma2(__float2half2_rn(-0.003464f), u,
                        __float2half2_rn( 0.013468f));
    p = __hfma2(p, u, __float2half2_rn(-0.055410f));
    p = __hfma2(p, u, __float2half2_rn( 0.333045f));
    p = __hfma2(p, u, __float2half2_rn( 0.405482f));
    return __hadd2(__hmax2(s, __float2half2_rn(0.0f)), p);
}
__device__ __forceinline__ uint32_t smem_u32(const void* p) {
    uint32_t a;
    asm("{ .reg .u64 t; cvta.to.shared.u64 t, %1; cvt.u32.u64 %0, t; }"
        : "=r"(a) : "l"(p));
    return a;
}
__device__ __forceinline__ uint32_t pkhf(float a, float b) {   // hi=a, lo=b
    uint32_t r; asm("cvt.rn.f16x2.f32 %0, %1, %2;" : "=r"(r) : "f"(a), "f"(b));
    return r;
}
__device__ __forceinline__ void ldsm4(uint32_t* r, uint32_t addr) {
    asm volatile("ldmatrix.sync.aligned.m8n8.x4.shared.b16 {%0,%1,%2,%3}, [%4];"
                 : "=r"(r[0]), "=r"(r[1]), "=r"(r[2]), "=r"(r[3]) : "r"(addr));
}
__device__ __forceinline__ void mma_f16(float* c, const uint32_t* a,
                                        uint32_t b0, uint32_t b1) {
    asm volatile(
        "mma.sync.aligned.m16n8k16.row.col.f32.f16.f16.f32 "
        "{%0,%1,%2,%3}, {%4,%5,%6,%7}, {%8,%9}, {%0,%1,%2,%3};"
        : "+f"(c[0]), "+f"(c[1]), "+f"(c[2]), "+f"(c[3])
        : "r"(a[0]), "r"(a[1]), "r"(a[2]), "r"(a[3]), "r"(b0), "r"(b1));
}

// ---- SMEM layout (bytes) per 256-thread CTA ----
// W1T: [192 n'][64 k] fp16, 128B rows, chunk xor ((n&7)<<4).
// W2T: [32 n][64 k] fp16, same layout (4KB) — layer-2 B frags via ldsm.
// cab: fp16 [16 rows][13 vecs][64], 128B vec-rows, slot xor ((vec^row)&7).
// h:   [8 warps][32 pair-rows][64 fp16], 128B rows, chunk xor ((p&7)<<4).
static constexpr int S_W1H   = 0;        // 24576
static constexpr int S_W2    = 24576;    // 4096
static constexpr int S_CAB   = 28672;    // 2 x 26624 = 53248
static constexpr int CAB_BUF = 26624;    //   16 rows * 13 vecs * 128B
static constexpr int S_H     = 81920;    // 8 warps x 4096 = 32768
static constexpr int SMEM_BYTES = 114688;

static constexpr int RPG = 16;           // rows per group (divides B)

__global__ void __launch_bounds__(256, 2) three_body_kernel(
    const float* __restrict__ core,   // [B, 64]
    const float* __restrict__ ligs,   // [B, 6, 64]
    const float* __restrict__ W1,     // [192, 64]
    const float* __restrict__ b1,     // [64]
    const float* __restrict__ W2,     // [64, 32]
    const float* __restrict__ b2,     // [32]
    const float* __restrict__ W3,     // [32]
    const float* __restrict__ b3,     // [1]
    float* __restrict__ out,          // [B]
    int B)
{
    extern __shared__ unsigned char sm[];
    const uint32_t smem_base = smem_u32(sm);
    const int tid  = threadIdx.x;
    const int lane = tid & 31;
    const int wid  = tid >> 5;        // 0..7

    // ---- stage W1^T (fp16, swizzled 128B rows) ----
    for (int idx = tid; idx < 12288; idx += 256) {
        int n = idx >> 6, k = idx & 63;
        float w;
        if      (n < 64)  w = W1[(64  + k) * 64 + n];
        else if (n < 128) w = W1[(128 + k) * 64 + (n - 64)];
        else              w = W1[k * 64 + (n - 128)];
        int byte = n * 128 + ((2 * k) ^ ((n & 7) << 4));
        *reinterpret_cast<__half*>(sm + S_W1H + byte) = __float2half_rn(w);
    }
    // ---- stage W2^T (fp16, same layout; layer-2 B operand) ----
    for (int idx = tid; idx < 2048; idx += 256) {
        int n = idx >> 6, k = idx & 63;
        int byte = n * 128 + ((2 * k) ^ ((n & 7) << 4));
        *reinterpret_cast<__half*>(sm + S_W2 + byte) =
            __float2half_rn(W2[k * 32 + n]);
    }

    int pi, pj;
    if (lane < 30) { pi = lane / 5; int jj = lane % 5; pj = jj + (jj >= pi ? 1 : 0); }
    else           { pi = 0; pj = 1; }

    const float b3v = b3[0];
    const int r0  = lane >> 2;            // fragment row in m16 (0..7)
    const int c0  = (lane & 3) * 2;       // fragment col pair base
    const uint32_t lsw   = (uint32_t)(lane & 7) << 4;
    const uint32_t csel  = (uint32_t)(lane >> 4) * 16;
    const uint32_t w1row = (uint32_t)(lane & 15) * 128;
    const uint32_t w1baseH = smem_base + S_W1H;
    const uint32_t w2base  = smem_base + S_W2;
    const uint32_t hbl  = smem_base + S_H + wid * 4096;
    char* hrow = (char*)sm + S_H + wid * 4096 + lane * 128;
    const uint32_t hsw = (uint32_t)(lane & 7) << 4;

    const int n_groups = B / RPG;   // 2048 exact

    // ---- phase 1: layer-1 GEMMs for group at rbase, into cab buffer cb ----
    auto phase1 = [&](int rbase, char* cb) {
        if (wid < 6) {   // ligand k = wid, M=16 tile (all rows real)
            const int k  = wid;
            const float* xa = ligs + (size_t)(rbase + r0) * 384 + k * 64;
            const float* xb = ligs + (size_t)(rbase + r0 + 8) * 384 + k * 64;
            uint32_t af[4][4];
            #pragma unroll
            for (int kt = 0; kt < 4; kt++) {
                int c = kt * 16 + c0;
                float2 x00 = *reinterpret_cast<const float2*>(xa + c);
                float2 x10 = *reinterpret_cast<const float2*>(xb + c);
                float2 x01 = *reinterpret_cast<const float2*>(xa + c + 8);
                float2 x11 = *reinterpret_cast<const float2*>(xb + c + 8);
                af[kt][0] = pkhf(x00.y, x00.x);  af[kt][1] = pkhf(x10.y, x10.x);
                af[kt][2] = pkhf(x01.y, x01.x);  af[kt][3] = pkhf(x11.y, x11.x);
            }
            #pragma unroll
            for (int np = 0; np < 8; np++) {
                float a0[4] = {0.f, 0.f, 0.f, 0.f}, a1[4] = {0.f, 0.f, 0.f, 0.f};
                #pragma unroll
                for (int kt = 0; kt < 4; kt++) {
                    uint32_t bh[4];
                    uint32_t adr = w1baseH + (uint32_t)np * 2048 + w1row
                                 + (((uint32_t)kt * 32 + csel) ^ lsw);
                    ldsm4(bh, adr);
                    mma_f16(a0, af[kt], bh[0], bh[2]);
                    mma_f16(a1, af[kt], bh[1], bh[3]);
                }
                #pragma unroll
                for (int ntl = 0; ntl < 2; ntl++) {
                    const float* a = ntl ? a1 : a0;
                    int n = np * 16 + ntl * 8 + c0;
                    int d = n & 63;
                    int vec = (n < 64) ? k : 6 + k;
                    uint32_t v0 = pkhf(a[1], a[0]);        // lo = d, hi = d+1
                    uint32_t v1 = pkhf(a[3], a[2]);
                    uint32_t off0 = (uint32_t)(2 * d)
                                  ^ ((uint32_t)((vec ^ r0) & 7) << 4);
                    uint32_t off1 = (uint32_t)(2 * d)
                                  ^ ((uint32_t)((vec ^ (r0 + 8)) & 7) << 4);
                    *reinterpret_cast<uint32_t*>(
                        cb + r0 * 1664 + vec * 128 + off0) = v0;
                    *reinterpret_cast<uint32_t*>(
                        cb + (r0 + 8) * 1664 + vec * 128 + off1) = v1;
                }
            }
        } else {   // core projection (+b1): warps 6,7 take 2 n-tiles each
            const float* xa = core + (size_t)(rbase + r0) * 64;
            const float* xb = core + (size_t)(rbase + r0 + 8) * 64;
            uint32_t af[4][4];
            #pragma unroll
            for (int kt = 0; kt < 4; kt++) {
                int c = kt * 16 + c0;
                float2 x00 = *reinterpret_cast<const float2*>(xa + c);
                float2 x10 = *reinterpret_cast<const float2*>(xb + c);
                float2 x01 = *reinterpret_cast<const float2*>(xa + c + 8);
                float2 x11 = *reinterpret_cast<const float2*>(xb + c + 8);
                af[kt][0] = pkhf(x00.y, x00.x);  af[kt][1] = pkhf(x10.y, x10.x);
                af[kt][2] = pkhf(x01.y, x01.x);  af[kt][3] = pkhf(x11.y, x11.x);
            }
            #pragma unroll
            for (int t = 0; t < 2; t++) {
                const int np = (wid - 6) * 2 + t;
                float a0[4] = {0.f, 0.f, 0.f, 0.f}, a1[4] = {0.f, 0.f, 0.f, 0.f};
                #pragma unroll
                for (int kt = 0; kt < 4; kt++) {
                    uint32_t bh[4];
                    uint32_t adr = w1baseH + (uint32_t)(128 + np * 16) * 128 + w1row
                                 + (((uint32_t)kt * 32 + csel) ^ lsw);
                    ldsm4(bh, adr);
                    mma_f16(a0, af[kt], bh[0], bh[2]);
                    mma_f16(a1, af[kt], bh[1], bh[3]);
                }
                #pragma unroll
                for (int ntl = 0; ntl < 2; ntl++) {
                    const float* a = ntl ? a1 : a0;
                    int d = np * 16 + ntl * 8 + c0;
                    float bb0 = __ldg(b1 + d), bb1 = __ldg(b1 + d + 1);
                    uint32_t v0 = pkhf(a[1] + bb1, a[0] + bb0);
                    uint32_t v1 = pkhf(a[3] + bb1, a[2] + bb0);
                    uint32_t off0 = (uint32_t)(2 * d)
                                  ^ ((uint32_t)((12 ^ r0) & 7) << 4);
                    uint32_t off1 = (uint32_t)(2 * d)
                                  ^ ((uint32_t)((12 ^ (r0 + 8)) & 7) << 4);
                    *reinterpret_cast<uint32_t*>(
                        cb + r0 * 1664 + 12 * 128 + off0) = v0;
                    *reinterpret_cast<uint32_t*>(
                        cb + (r0 + 8) * 1664 + 12 * 128 + off1) = v1;
                }
            }
        }
    };

    // ---- phase 2: h-build + layer-2 GEMM + epilogue for group at rbase ----
    auto phase2 = [&](int rbase, const char* cb) {
        #pragma unroll
        for (int rr = 0; rr < 2; rr++) {
            const int row = wid * 2 + rr;
            const char* rowb = cb + row * 1664;
            const char* bA = rowb + pi * 128;
            const char* bB = rowb + (6 + pj) * 128;
            const char* bC = rowb + 12 * 128;
            const uint32_t swA = (uint32_t)((pi ^ row) & 7) << 4;
            const uint32_t swB = (uint32_t)(((6 + pj) ^ row) & 7) << 4;
            const uint32_t swC = (uint32_t)((12 ^ row) & 7) << 4;

            #pragma unroll
            for (int q2 = 0; q2 < 8; q2++) {
                const uint32_t qb = (uint32_t)q2 * 16;
                uint4 ua = *reinterpret_cast<const uint4*>(bA + (qb ^ swA));
                uint4 ub = *reinterpret_cast<const uint4*>(bB + (qb ^ swB));
                uint4 uc = *reinterpret_cast<const uint4*>(bC + (qb ^ swC));
                const __half2* ha = reinterpret_cast<const __half2*>(&ua);
                const __half2* hb2 = reinterpret_cast<const __half2*>(&ub);
                const __half2* hc = reinterpret_cast<const __half2*>(&uc);
                uint32_t hw[4];
                #pragma unroll
                for (int w = 0; w < 4; w++) {
                    __half2 s = __hadd2(__hadd2(ha[w], hb2[w]), hc[w]);
                    __half2 r = softplus_h2(s);
                    hw[w] = *reinterpret_cast<uint32_t*>(&r);
                }
                *reinterpret_cast<uint4*>(hrow + (qb ^ hsw)) =
                    make_uint4(hw[0], hw[1], hw[2], hw[3]);
            }
            __syncwarp();

            float acc[2][4][4];
            #pragma unroll
            for (int mt = 0; mt < 2; mt++)
                #pragma unroll
                for (int nt = 0; nt < 4; nt++)
                    #pragma unroll
                    for (int e = 0; e < 4; e++) acc[mt][nt][e] = 0.0f;

            // kt outer; W2 B-frags loaded once per kt, shared by both mt
            #pragma unroll
            for (int kt = 0; kt < 4; kt++) {
                uint32_t b0f[4], b1f4[4];
                uint32_t kofs = ((uint32_t)kt * 32 + csel) ^ lsw;
                ldsm4(b0f,  w2base + w1row + kofs);           // n 0..15
                ldsm4(b1f4, w2base + 2048 + w1row + kofs);    // n 16..31
                #pragma unroll
                for (int mt = 0; mt < 2; mt++) {
                    uint32_t afr[4];
                    ldsm4(afr, hbl + (uint32_t)mt * 2048 + w1row + kofs);
                    mma_f16(acc[mt][0], afr, b0f[0],  b0f[2]);
                    mma_f16(acc[mt][1], afr, b0f[1],  b0f[3]);
                    mma_f16(acc[mt][2], afr, b1f4[0], b1f4[2]);
                    mma_f16(acc[mt][3], afr, b1f4[1], b1f4[3]);
                }
            }

            float total = 0.0f;
            #pragma unroll
            for (int mt = 0; mt < 2; mt++)
                #pragma unroll
                for (int hf = 0; hf < 2; hf++) {
                    int prow = mt * 16 + (lane >> 2) + hf * 8;
                    float part = 0.0f;
                    #pragma unroll
                    for (int nt = 0; nt < 4; nt++)
                        #pragma unroll
                        for (int e = 0; e < 2; e++) {
                            int nn = nt * 8 + c0 + e;
                            part += softplus_f(acc[mt][nt][hf * 2 + e]
                                               + __ldg(b2 + nn)) * __ldg(W3 + nn);
                        }
                    if (prow < 30) total += part;
                }
            #pragma unroll
            for (int off = 16; off; off >>= 1)
                total += __shfl_xor_sync(FULLMASK, total, off);
            if (lane == 0)
                out[rbase + row] = 0.5f * total + 15.0f * b3v;
            __syncwarp();   // h buffer free before next row overwrites it
        }
    };

    __syncthreads();   // weights staged

    // ---- pipelined main loop: 1 barrier per group ----
    char* cab = (char*)sm + S_CAB;
    int g = blockIdx.x;
    if (g < n_groups) phase1(g * RPG, cab);         // prologue -> buffer 0
    int it = 0;
    for (; g < n_groups; g += gridDim.x, it++) {
        __syncthreads();   // prev phase1 (buf it&1) + prev phase2 (buf (it+1)&1) done
        int gn = g + gridDim.x;
        if (gn < n_groups) phase1(gn * RPG, cab + ((it + 1) & 1) * CAB_BUF);
        phase2(g * RPG, cab + (it & 1) * CAB_BUF);
    }
}

extern "C" void kernel_launch(void* const* d_in, const int* in_sizes, int n_in,
                              void* d_out, int out_size) {
    const float* core = (const float*)d_in[0];
    const float* ligs = (const float*)d_in[1];
    const float* W1   = (const float*)d_in[2];
    const float* b1   = (const float*)d_in[3];
    const float* W2   = (const float*)d_in[4];
    const float* b2   = (const float*)d_in[5];
    const float* W3   = (const float*)d_in[6];
    const float* b3   = (const float*)d_in[7];
    float* out = (float*)d_out;

    const int B = in_sizes[0] / 64;   // 32768

    cudaFuncSetAttribute(three_body_kernel,
                         cudaFuncAttributeMaxDynamicSharedMemorySize, SMEM_BYTES);

    // 296 CTAs = 2 per SM (114.7KB SMEM, <=128 regs); 2048 groups of 16 rows.
    three_body_kernel<<<296, 256, SMEM_BYTES>>>(
        core, ligs, W1, b1, W2, b2, W3, b3, out, B);
}